// round 1
// baseline (speedup 1.0000x reference)
#include <cuda_runtime.h>

// Problem constants
#define Hh     51
#define H4     204          // 4*H
#define BATCH  1024
#define TT     1024
#define MB     8            // batch elements per CTA
#define NCTA   (BATCH / MB) // 128
#define NTHR   224          // 7 warps; threads 0..203 do matmuls

// ---- shared memory layout (float offsets) ----
// sW1  : [204][52]  W_hh1 rows, col 51 zero-padded (stride 52 -> LDS.128 conflict-free)
// sW2  : [204][108] cols 0..50 = W_ih2 row, 51=0, 52..102 = W_hh2 row, 103=0 (stride 108 conflict-free)
// sWih1: [204], sB1/sB2: [204] combined biases, sWlin: [52]
// sX   : [8][1024] this CTA's input slice
// sH12 : [104][8]  rows 0..50 h1, 51=0, 52..102 h2, 103=0
// sC   : [2][51][8]
// sG   : [204][12] gate staging (stride 12 -> STS.128 conflict-free)
#define OFF_W1    0
#define OFF_W2    10608
#define OFF_WIH1  32640
#define OFF_B1    32844
#define OFF_B2    33048
#define OFF_WLIN  33252
#define OFF_X     33304
#define OFF_H12   41496
#define OFF_C     42328
#define OFF_G     43144
#define SMEM_FLOATS 45592
#define SMEM_BYTES  (SMEM_FLOATS * 4)

__device__ __forceinline__ float sigf(float x) {
    // sigmoid via fast exp + fast divide (~1e-6 rel err, saturates correctly)
    return __fdividef(1.0f, 1.0f + __expf(-x));
}
__device__ __forceinline__ float tanhfast(float x) {
    // tanh(x) = 1 - 2/(exp(2x)+1); correct at +/-inf via IEEE exp behavior
    return 1.0f - __fdividef(2.0f, __expf(2.0f * x) + 1.0f);
}

__global__ __launch_bounds__(NTHR, 1)
void lstm_seq_kernel(const float* __restrict__ input,
                     const float* __restrict__ W_ih1, const float* __restrict__ W_hh1,
                     const float* __restrict__ b_ih1, const float* __restrict__ b_hh1,
                     const float* __restrict__ W_ih2, const float* __restrict__ W_hh2,
                     const float* __restrict__ b_ih2, const float* __restrict__ b_hh2,
                     const float* __restrict__ W_lin, const float* __restrict__ b_lin,
                     float* __restrict__ out)
{
    extern __shared__ float sm[];
    float* sW1   = sm + OFF_W1;
    float* sW2   = sm + OFF_W2;
    float* sWih1 = sm + OFF_WIH1;
    float* sB1   = sm + OFF_B1;
    float* sB2   = sm + OFF_B2;
    float* sWlin = sm + OFF_WLIN;
    float* sX    = sm + OFF_X;
    float* sH12  = sm + OFF_H12;
    float* sC    = sm + OFF_C;
    float* sG    = sm + OFF_G;

    const int tid = threadIdx.x;
    const int b0  = blockIdx.x * MB;

    // ---------------- one-time staging ----------------
    for (int i = tid; i < H4 * Hh; i += NTHR) {
        int r = i / Hh, k = i % Hh;
        sW1[r * 52 + k]        = W_hh1[i];
        sW2[r * 108 + k]       = W_ih2[i];
        sW2[r * 108 + 52 + k]  = W_hh2[i];
    }
    for (int r = tid; r < H4; r += NTHR) {
        sW1[r * 52 + 51]   = 0.0f;
        sW2[r * 108 + 51]  = 0.0f;
        sW2[r * 108 + 103] = 0.0f;
        sWih1[r] = W_ih1[r];                  // W_ih1 is [204,1]
        sB1[r]   = b_ih1[r] + b_hh1[r];
        sB2[r]   = b_ih2[r] + b_hh2[r];
    }
    if (tid < Hh) sWlin[tid] = W_lin[tid];
    // contiguous input slice for this CTA: rows b0..b0+7
    for (int i = tid; i < MB * TT; i += NTHR) sX[i] = input[b0 * TT + i];
    // zero states (includes pad rows 51 and 103 of sH12)
    for (int i = tid; i < 104 * MB; i += NTHR) sH12[i] = 0.0f;
    for (int i = tid; i < 2 * Hh * MB; i += NTHR) sC[i] = 0.0f;

    const float blin = b_lin[0];
    __syncthreads();

    // ---------------- time loop ----------------
    for (int t = 0; t < TT; ++t) {
        // ---- layer 1 gates: G[r][b] = b1[r] + Wih1[r]*x_t[b] + sum_k W_hh1[r][k]*h1[k][b]
        if (tid < H4) {
            const int r = tid;
            const float bias = sB1[r];
            const float wih  = sWih1[r];
            float acc[8];
            #pragma unroll
            for (int b = 0; b < 8; ++b)
                acc[b] = fmaf(wih, sX[b * TT + t], bias);

            const float* wrow = sW1 + r * 52;
            #pragma unroll
            for (int kk = 0; kk < 13; ++kk) {
                const float4 w4 = *reinterpret_cast<const float4*>(wrow + kk * 4);
                const float wv[4] = {w4.x, w4.y, w4.z, w4.w};
                #pragma unroll
                for (int dk = 0; dk < 4; ++dk) {
                    const float* hrow = sH12 + (kk * 4 + dk) * 8;
                    const float4 hA = *reinterpret_cast<const float4*>(hrow);
                    const float4 hB = *reinterpret_cast<const float4*>(hrow + 4);
                    acc[0] = fmaf(wv[dk], hA.x, acc[0]);
                    acc[1] = fmaf(wv[dk], hA.y, acc[1]);
                    acc[2] = fmaf(wv[dk], hA.z, acc[2]);
                    acc[3] = fmaf(wv[dk], hA.w, acc[3]);
                    acc[4] = fmaf(wv[dk], hB.x, acc[4]);
                    acc[5] = fmaf(wv[dk], hB.y, acc[5]);
                    acc[6] = fmaf(wv[dk], hB.z, acc[6]);
                    acc[7] = fmaf(wv[dk], hB.w, acc[7]);
                }
            }
            float4* gp = reinterpret_cast<float4*>(sG + r * 12);
            gp[0] = make_float4(acc[0], acc[1], acc[2], acc[3]);
            gp[1] = make_float4(acc[4], acc[5], acc[6], acc[7]);
        }
        __syncthreads();

        // ---- layer 1 state update: h1, c1
        for (int idx = tid; idx < Hh * MB; idx += NTHR) {
            const int j = idx >> 3, b = idx & 7;
            const float gi = sG[(j) * 12 + b];
            const float gf = sG[(Hh + j) * 12 + b];
            const float gg = sG[(2 * Hh + j) * 12 + b];
            const float go = sG[(3 * Hh + j) * 12 + b];
            const float iv = sigf(gi);
            const float fv = sigf(gf);
            const float gv = tanhfast(gg);
            const float ov = sigf(go);
            const float c  = fv * sC[idx] + iv * gv;
            sC[idx]   = c;
            sH12[idx] = ov * tanhfast(c);   // h1 rows 0..50
        }
        __syncthreads();

        // ---- layer 2 gates: input = [h1_new ; h2_old] (rows 0..103 of sH12)
        if (tid < H4) {
            const int r = tid;
            const float bias = sB2[r];
            float acc[8];
            #pragma unroll
            for (int b = 0; b < 8; ++b) acc[b] = bias;

            const float* wrow = sW2 + r * 108;
            #pragma unroll
            for (int kk = 0; kk < 26; ++kk) {
                const float4 w4 = *reinterpret_cast<const float4*>(wrow + kk * 4);
                const float wv[4] = {w4.x, w4.y, w4.z, w4.w};
                #pragma unroll
                for (int dk = 0; dk < 4; ++dk) {
                    const float* hrow = sH12 + (kk * 4 + dk) * 8;
                    const float4 hA = *reinterpret_cast<const float4*>(hrow);
                    const float4 hB = *reinterpret_cast<const float4*>(hrow + 4);
                    acc[0] = fmaf(wv[dk], hA.x, acc[0]);
                    acc[1] = fmaf(wv[dk], hA.y, acc[1]);
                    acc[2] = fmaf(wv[dk], hA.z, acc[2]);
                    acc[3] = fmaf(wv[dk], hA.w, acc[3]);
                    acc[4] = fmaf(wv[dk], hB.x, acc[4]);
                    acc[5] = fmaf(wv[dk], hB.y, acc[5]);
                    acc[6] = fmaf(wv[dk], hB.z, acc[6]);
                    acc[7] = fmaf(wv[dk], hB.w, acc[7]);
                }
            }
            float4* gp = reinterpret_cast<float4*>(sG + r * 12);
            gp[0] = make_float4(acc[0], acc[1], acc[2], acc[3]);
            gp[1] = make_float4(acc[4], acc[5], acc[6], acc[7]);
        }
        __syncthreads();

        // ---- layer 2 state update: h2, c2
        for (int idx = tid; idx < Hh * MB; idx += NTHR) {
            const int j = idx >> 3, b = idx & 7;
            const float gi = sG[(j) * 12 + b];
            const float gf = sG[(Hh + j) * 12 + b];
            const float gg = sG[(2 * Hh + j) * 12 + b];
            const float go = sG[(3 * Hh + j) * 12 + b];
            const float iv = sigf(gi);
            const float fv = sigf(gf);
            const float gv = tanhfast(gg);
            const float ov = sigf(go);
            const float c  = fv * sC[Hh * MB + idx] + iv * gv;
            sC[Hh * MB + idx]      = c;
            sH12[(52 + j) * 8 + b] = ov * tanhfast(c);   // h2 rows 52..102
        }
        __syncthreads();

        // ---- output head: y[b] = W_lin . h2_new[:,b] + b_lin
        // Safe w.r.t. next iteration: L1 gates only read rows 0..51, and the next
        // write to h2 rows happens after two more barriers.
        if (tid < MB) {
            const int b = tid;
            float s = blin;
            #pragma unroll
            for (int j = 0; j < Hh; ++j)
                s = fmaf(sWlin[j], sH12[(52 + j) * 8 + b], s);
            out[(b0 + b) * TT + t] = s;
        }
    }
}

extern "C" void kernel_launch(void* const* d_in, const int* in_sizes, int n_in,
                              void* d_out, int out_size) {
    const float* input = (const float*)d_in[0];
    const float* W_ih1 = (const float*)d_in[1];
    const float* W_hh1 = (const float*)d_in[2];
    const float* b_ih1 = (const float*)d_in[3];
    const float* b_hh1 = (const float*)d_in[4];
    const float* W_ih2 = (const float*)d_in[5];
    const float* W_hh2 = (const float*)d_in[6];
    const float* b_ih2 = (const float*)d_in[7];
    const float* b_hh2 = (const float*)d_in[8];
    const float* W_lin = (const float*)d_in[9];
    const float* b_lin = (const float*)d_in[10];
    float* out = (float*)d_out;

    cudaFuncSetAttribute(lstm_seq_kernel,
                         cudaFuncAttributeMaxDynamicSharedMemorySize, SMEM_BYTES);
    lstm_seq_kernel<<<NCTA, NTHR, SMEM_BYTES>>>(
        input, W_ih1, W_hh1, b_ih1, b_hh1,
        W_ih2, W_hh2, b_ih2, b_hh2, W_lin, b_lin, out);
}

// round 2
// speedup vs baseline: 1.3199x; 1.3199x over previous
#include <cuda_runtime.h>

// Problem constants
#define Hh     51
#define H4     204          // 4*H
#define TT     1024
#define MB     8            // batch elements per CTA
#define NCTA   128          // 1024 / MB
#define NTHR   416          // 13 warps
#define NWORK  408          // 4 k-groups x 102 row-pairs

// ---- shared memory layout (float offsets) ----
// sW1  : [204][52]  W_hh1 rows, col 51 zero (stride 52 -> conflict-free LDS.128)
// sB1/sB2 : [204] combined biases; sWlin : [51]
// sX   : [1024][8]  input transposed (t-major) for vector broadcast loads
// sH12 : [112][8]   rows 0..50 h1, 51 zero, 52..102 h2, 103..111 zero
// sC   : [2][51][8]
// sG   : [4][204][12]  per-k-group partial gates (stride 12 -> conflict-free STS.128)
#define OFF_W1    0
#define OFF_B1    10608
#define OFF_B2    10812
#define OFF_WLIN  11016
#define OFF_X     11072
#define OFF_H12   19264
#define OFF_C     20160
#define OFF_G     20976
#define SMEM_FLOATS 30768
#define SMEM_BYTES  (SMEM_FLOATS * 4)

typedef unsigned long long u64;

__device__ __forceinline__ u64 splat2(float w) {
    unsigned int wi = __float_as_uint(w);
    u64 r;
    asm("mov.b64 %0, {%1, %1};" : "=l"(r) : "r"(wi));
    return r;
}
__device__ __forceinline__ void ffma2(u64& d, u64 a, u64 b) {
    asm("fma.rn.f32x2 %0, %1, %2, %0;" : "+l"(d) : "l"(a), "l"(b));
}

__device__ __forceinline__ float sigf(float x) {
    return __fdividef(1.0f, 1.0f + __expf(-x));
}
__device__ __forceinline__ float tanhfast(float x) {
    return 1.0f - __fdividef(2.0f, __expf(2.0f * x) + 1.0f);
}

__global__ __launch_bounds__(NTHR, 1)
void lstm_seq_kernel(const float* __restrict__ input,
                     const float* __restrict__ W_ih1, const float* __restrict__ W_hh1,
                     const float* __restrict__ b_ih1, const float* __restrict__ b_hh1,
                     const float* __restrict__ W_ih2, const float* __restrict__ W_hh2,
                     const float* __restrict__ b_ih2, const float* __restrict__ b_hh2,
                     const float* __restrict__ W_lin, const float* __restrict__ b_lin,
                     float* __restrict__ out)
{
    extern __shared__ float sm[];
    float* sW1   = sm + OFF_W1;
    float* sB1   = sm + OFF_B1;
    float* sB2   = sm + OFF_B2;
    float* sWlin = sm + OFF_WLIN;
    float* sX    = sm + OFF_X;
    float* sH12  = sm + OFF_H12;
    float* sC    = sm + OFF_C;
    float* sG    = sm + OFF_G;

    const int tid = threadIdx.x;
    const int b0  = blockIdx.x * MB;

    // ---------------- one-time staging ----------------
    for (int i = tid; i < H4 * Hh; i += NTHR) {
        int r = i / Hh, k = i % Hh;
        sW1[r * 52 + k] = W_hh1[i];
    }
    for (int r = tid; r < H4; r += NTHR) {
        sW1[r * 52 + 51] = 0.0f;
        sB1[r] = b_ih1[r] + b_hh1[r];
        sB2[r] = b_ih2[r] + b_hh2[r];
    }
    if (tid < Hh) sWlin[tid] = W_lin[tid];
    // transpose input slice: sX[t][b]
    for (int i = tid; i < MB * TT; i += NTHR) {
        int b = i >> 10, t = i & 1023;
        sX[t * MB + b] = input[b0 * TT + i];
    }
    for (int i = tid; i < 112 * MB; i += NTHR) sH12[i] = 0.0f;
    for (int i = tid; i < 2 * Hh * MB; i += NTHR) sC[i] = 0.0f;

    // ---------------- per-thread work assignment + register weights ----------------
    int g = 0, r0 = 0, r1 = 102, b1k = 0, cnt1 = 4, b2k = 0, cnt2 = 7;
    float wih1_0 = 0.0f, wih1_1 = 0.0f;
    float wB0[28], wB1[28];   // layer-2 weights, register-resident
    #pragma unroll
    for (int i = 0; i < 28; ++i) { wB0[i] = 0.0f; wB1[i] = 0.0f; }

    if (tid < NWORK) {
        g  = tid / 102;
        int j = tid % 102;
        r0 = j; r1 = j + 102;
        b1k  = (g == 0) ? 0 : (3 * g + 1);     // {0,4,7,10}
        cnt1 = (g == 0) ? 4 : 3;               // {4,3,3,3}
        b2k  = (g < 2) ? (7 * g) : (6 * g + 2); // {0,7,14,20}
        cnt2 = (g < 2) ? 7 : 6;                // {7,7,6,6}
        wih1_0 = W_ih1[r0];
        wih1_1 = W_ih1[r1];
        #pragma unroll
        for (int s = 0; s < 7; ++s) {
            #pragma unroll
            for (int dk = 0; dk < 4; ++dk) {
                int col = (b2k + s) * 4 + dk;
                float v0 = 0.0f, v1 = 0.0f;
                if (s < cnt2) {
                    if (col < 51) {
                        v0 = W_ih2[r0 * 51 + col];
                        v1 = W_ih2[r1 * 51 + col];
                    } else if (col >= 52 && col < 103) {
                        v0 = W_hh2[r0 * 51 + col - 52];
                        v1 = W_hh2[r1 * 51 + col - 52];
                    }
                }
                wB0[s * 4 + dk] = v0;
                wB1[s * 4 + dk] = v1;
            }
        }
    }
    const float* sW1r0 = sW1 + r0 * 52;
    const float* sW1r1 = sW1 + r1 * 52;
    const float blin = b_lin[0];
    __syncthreads();

    // ---------------- time loop ----------------
    for (int t = 0; t < TT; ++t) {
        // ===== layer 1 partial gates (k-group g, rows r0,r1) =====
        if (tid < NWORK) {
            u64 a0[4] = {0, 0, 0, 0}, a1[4] = {0, 0, 0, 0};
            if (g == 0) {
                const ulonglong2* xp = (const ulonglong2*)(sX + t * MB);
                ulonglong2 xL = xp[0], xH = xp[1];
                u64 w0 = splat2(wih1_0), w1 = splat2(wih1_1);
                ffma2(a0[0], w0, xL.x); ffma2(a0[1], w0, xL.y);
                ffma2(a0[2], w0, xH.x); ffma2(a0[3], w0, xH.y);
                ffma2(a1[0], w1, xL.x); ffma2(a1[1], w1, xL.y);
                ffma2(a1[2], w1, xH.x); ffma2(a1[3], w1, xH.y);
            }
            #pragma unroll
            for (int s = 0; s < 4; ++s) {
                if (s < cnt1) {
                    const int kk = b1k + s;
                    const float4 wv0 = *(const float4*)(sW1r0 + kk * 4);
                    const float4 wv1 = *(const float4*)(sW1r1 + kk * 4);
                    const float wz0[4] = {wv0.x, wv0.y, wv0.z, wv0.w};
                    const float wz1[4] = {wv1.x, wv1.y, wv1.z, wv1.w};
                    #pragma unroll
                    for (int dk = 0; dk < 4; ++dk) {
                        const float* hr = sH12 + (kk * 4 + dk) * MB;
                        const ulonglong2 hL = *(const ulonglong2*)hr;
                        const ulonglong2 hH = *(const ulonglong2*)(hr + 4);
                        const u64 p0 = splat2(wz0[dk]);
                        ffma2(a0[0], p0, hL.x); ffma2(a0[1], p0, hL.y);
                        ffma2(a0[2], p0, hH.x); ffma2(a0[3], p0, hH.y);
                        const u64 p1 = splat2(wz1[dk]);
                        ffma2(a1[0], p1, hL.x); ffma2(a1[1], p1, hL.y);
                        ffma2(a1[2], p1, hH.x); ffma2(a1[3], p1, hH.y);
                    }
                }
            }
            ulonglong2* q = (ulonglong2*)(sG + (g * H4 + r0) * 12);
            ulonglong2 v;
            v.x = a0[0]; v.y = a0[1]; q[0] = v;
            v.x = a0[2]; v.y = a0[3]; q[1] = v;
            q = (ulonglong2*)(sG + (g * H4 + r1) * 12);
            v.x = a1[0]; v.y = a1[1]; q[0] = v;
            v.x = a1[2]; v.y = a1[3]; q[1] = v;
        }
        __syncthreads();

        // ===== layer 1 state update =====
        if (tid < NWORK) {
            const int j = tid >> 3, b = tid & 7;
            #define GS(row) (sG[(row) * 12 + b] + sG[2448 + (row) * 12 + b] + \
                             sG[4896 + (row) * 12 + b] + sG[7344 + (row) * 12 + b])
            const float gi = sB1[j]       + GS(j);
            const float gf = sB1[51 + j]  + GS(51 + j);
            const float gg = sB1[102 + j] + GS(102 + j);
            const float go = sB1[153 + j] + GS(153 + j);
            const float iv = sigf(gi), fv = sigf(gf);
            const float gv = tanhfast(gg), ov = sigf(go);
            const float c = fv * sC[tid] + iv * gv;
            sC[tid]   = c;
            sH12[tid] = ov * tanhfast(c);     // h1 rows 0..50
        }
        __syncthreads();

        // ===== layer 2 partial gates (weights in registers) =====
        if (tid < NWORK) {
            u64 a0[4] = {0, 0, 0, 0}, a1[4] = {0, 0, 0, 0};
            #pragma unroll
            for (int s = 0; s < 7; ++s) {
                if (s < cnt2) {
                    const int kk = b2k + s;
                    #pragma unroll
                    for (int dk = 0; dk < 4; ++dk) {
                        const float* hr = sH12 + (kk * 4 + dk) * MB;
                        const ulonglong2 hL = *(const ulonglong2*)hr;
                        const ulonglong2 hH = *(const ulonglong2*)(hr + 4);
                        const u64 p0 = splat2(wB0[s * 4 + dk]);
                        ffma2(a0[0], p0, hL.x); ffma2(a0[1], p0, hL.y);
                        ffma2(a0[2], p0, hH.x); ffma2(a0[3], p0, hH.y);
                        const u64 p1 = splat2(wB1[s * 4 + dk]);
                        ffma2(a1[0], p1, hL.x); ffma2(a1[1], p1, hL.y);
                        ffma2(a1[2], p1, hH.x); ffma2(a1[3], p1, hH.y);
                    }
                }
            }
            ulonglong2* q = (ulonglong2*)(sG + (g * H4 + r0) * 12);
            ulonglong2 v;
            v.x = a0[0]; v.y = a0[1]; q[0] = v;
            v.x = a0[2]; v.y = a0[3]; q[1] = v;
            q = (ulonglong2*)(sG + (g * H4 + r1) * 12);
            v.x = a1[0]; v.y = a1[1]; q[0] = v;
            v.x = a1[2]; v.y = a1[3]; q[1] = v;
        }
        __syncthreads();

        // ===== layer 2 state update =====
        if (tid < NWORK) {
            const int j = tid >> 3, b = tid & 7;
            const float gi = sB2[j]       + GS(j);
            const float gf = sB2[51 + j]  + GS(51 + j);
            const float gg = sB2[102 + j] + GS(102 + j);
            const float go = sB2[153 + j] + GS(153 + j);
            #undef GS
            const float iv = sigf(gi), fv = sigf(gf);
            const float gv = tanhfast(gg), ov = sigf(go);
            const float c = fv * sC[Hh * MB + tid] + iv * gv;
            sC[Hh * MB + tid]        = c;
            sH12[(52 + j) * MB + b]  = ov * tanhfast(c);   // h2 rows 52..102
        }
        __syncthreads();

        // ===== output head (reads h2; no conflict with next gate1 which only writes sG) =====
        if (tid < MB) {
            const int b = tid;
            float s = blin;
            #pragma unroll
            for (int j = 0; j < Hh; ++j)
                s = fmaf(sWlin[j], sH12[(52 + j) * MB + b], s);
            out[(b0 + b) * TT + t] = s;
        }
    }
}

extern "C" void kernel_launch(void* const* d_in, const int* in_sizes, int n_in,
                              void* d_out, int out_size) {
    const float* input = (const float*)d_in[0];
    const float* W_ih1 = (const float*)d_in[1];
    const float* W_hh1 = (const float*)d_in[2];
    const float* b_ih1 = (const float*)d_in[3];
    const float* b_hh1 = (const float*)d_in[4];
    const float* W_ih2 = (const float*)d_in[5];
    const float* W_hh2 = (const float*)d_in[6];
    const float* b_ih2 = (const float*)d_in[7];
    const float* b_hh2 = (const float*)d_in[8];
    const float* W_lin = (const float*)d_in[9];
    const float* b_lin = (const float*)d_in[10];
    float* out = (float*)d_out;

    cudaFuncSetAttribute(lstm_seq_kernel,
                         cudaFuncAttributeMaxDynamicSharedMemorySize, SMEM_BYTES);
    lstm_seq_kernel<<<NCTA, NTHR, SMEM_BYTES>>>(
        input, W_ih1, W_hh1, b_ih1, b_hh1,
        W_ih2, W_hh2, b_ih2, b_hh2, W_lin, b_lin, out);
}